// round 15
// baseline (speedup 1.0000x reference)
#include <cuda_runtime.h>
#include <cuda_bf16.h>
#include <cstdint>
#include <cstddef>

// ---------------- tile config ----------------
#define BM 128
#define BN 128
#define BK 64                        // bf16 per K-chunk (128 B rows)
#define NST 3
#define NTHR 128
#define A_ST (BM*BK*2)               // 16384 B
#define B_ST (BN*BK*2)               // 16384 B
#define ST_BYTES (A_ST + B_ST)       // 32768 B
#define SMEM_SZ (NST*ST_BYTES)       // 98304 B  (x2 CTAs = 196KB/SM)

// ---------------- static scratch (no allocations allowed) ----------------
__device__ __nv_bfloat16 g_actP[(size_t)8192*4096];
__device__ __nv_bfloat16 g_actQ[(size_t)8192*4096];
__device__ __nv_bfloat16 g_wt[(size_t)4096*4096];   // W^T: [N,K] K-major, bf16
__device__ float g_bias[4096];
__device__ float g_ea[4352];
__device__ float g_eb[4096];

// ---------------- helpers ----------------
__device__ __forceinline__ uint32_t smem_u32(const void* p) {
    uint32_t a;
    asm("{ .reg .u64 t; cvta.to.shared.u64 t, %1; cvt.u32.u64 %0, t; }" : "=r"(a) : "l"(p));
    return a;
}
__device__ __forceinline__ void cpa16(uint32_t s, const void* g) {
    asm volatile("cp.async.cg.shared.global [%0], [%1], 16;" :: "r"(s), "l"(g) : "memory");
}
#define LDMX4(r, addr) \
    asm volatile("ldmatrix.sync.aligned.m8n8.x4.shared.b16 {%0,%1,%2,%3}, [%4];" \
        : "=r"((r)[0]), "=r"((r)[1]), "=r"((r)[2]), "=r"((r)[3]) : "r"(addr))
#define MMAB16(c, a, b0, b1) \
    asm volatile("mma.sync.aligned.m16n8k16.row.col.f32.bf16.bf16.f32 " \
        "{%0,%1,%2,%3},{%4,%5,%6,%7},{%8,%9},{%0,%1,%2,%3};" \
        : "+f"((c)[0]), "+f"((c)[1]), "+f"((c)[2]), "+f"((c)[3]) \
        : "r"((a)[0]), "r"((a)[1]), "r"((a)[2]), "r"((a)[3]), "r"(b0), "r"(b1))

// ---------------- small kernels ----------------
__global__ void expfuse_k(const float* __restrict__ u, const float* __restrict__ v,
                          float* __restrict__ ea, float* __restrict__ eb,
                          int nu, int nv) {
    int i = blockIdx.x * blockDim.x + threadIdx.x;
    if (i < nu) ea[i] = expf(0.5f * u[i]);
    if (i < nv) eb[i] = expf(0.5f * v[i]);
}

__global__ void cvt_k(const float* __restrict__ in, __nv_bfloat16* __restrict__ out, int n4) {
    int i = blockIdx.x * blockDim.x + threadIdx.x;
    if (i < n4) {
        float4 v = ((const float4*)in)[i];
        __nv_bfloat162 h0, h1;
        h0.x = __float2bfloat16_rn(v.x); h0.y = __float2bfloat16_rn(v.y);
        h1.x = __float2bfloat16_rn(v.z); h1.y = __float2bfloat16_rn(v.w);
        ((__nv_bfloat162*)out)[2*i]   = h0;
        ((__nv_bfloat162*)out)[2*i+1] = h1;
    }
}

// W^T build: read M/eps row-major [fin,N], write g_wt [N,K] K-major (bf16) + bias (fp32)
__global__ void build_k(const float* __restrict__ M, const float* __restrict__ E,
                        const float* __restrict__ ea, const float* __restrict__ eb,
                        __nv_bfloat16* __restrict__ wt, float* __restrict__ bias,
                        int K, int N) {
    __shared__ float t[32][33];
    int c0 = blockIdx.x * 32, r0 = blockIdx.y * 32;
    int tx = threadIdx.x, ty = threadIdx.y;
    int c = c0 + tx;
    float ebc = eb[c];
    #pragma unroll
    for (int i = 0; i < 4; i++) {
        int r = r0 + ty + i * 8;
        if (r <= K) {
            size_t idx = (size_t)r * N + c;
            float val = fmaf(ea[r] * E[idx], ebc, M[idx]);
            if (r < K) t[ty + i * 8][tx] = val;
            else       bias[c] = val;
        }
    }
    __syncthreads();
    #pragma unroll
    for (int i = 0; i < 4; i++) {
        int n = c0 + ty + i * 8;
        int k = r0 + tx;
        if (k < K) wt[(size_t)n * K + k] = __float2bfloat16_rn(t[tx][ty + i * 8]);
    }
}

// ---------------- GEMM: C[8192,N] = A[8192,K] @ W^T + bias (+relu) ----------------
__device__ __forceinline__ void load_stage(uint32_t sb, int stage, int kc,
    const __nv_bfloat16* __restrict__ A, const __nv_bfloat16* __restrict__ W,
    int K, int m0, int n0, int tid) {
    // A: 128 rows x 128 B = 1024 chunks of 16B; 8 per thread
    const __nv_bfloat16* ga = A + (size_t)m0 * K + (size_t)kc * BK;
    uint32_t ab = sb + stage * ST_BYTES;
    #pragma unroll
    for (int j = 0; j < 8; j++) {
        int idx = tid + j * NTHR;
        int row = idx >> 3, c16 = idx & 7;
        uint32_t off = (uint32_t)(row * 128 + ((c16 ^ (row & 7)) << 4));
        cpa16(ab + off, ga + (size_t)row * K + c16 * 8);
    }
    // B: 128 rows x 128 B; 8 per thread
    const __nv_bfloat16* gb = W + (size_t)n0 * K + (size_t)kc * BK;
    uint32_t bb = ab + A_ST;
    #pragma unroll
    for (int j = 0; j < 8; j++) {
        int idx = tid + j * NTHR;
        int row = idx >> 3, c16 = idx & 7;
        uint32_t off = (uint32_t)(row * 128 + ((c16 ^ (row & 7)) << 4));
        cpa16(bb + off, gb + (size_t)row * K + c16 * 8);
    }
}

__global__ void __launch_bounds__(NTHR, 2) gemm_k(
    const __nv_bfloat16* __restrict__ A, const __nv_bfloat16* __restrict__ W,
    const float* __restrict__ bias, float* __restrict__ outF,
    __nv_bfloat16* __restrict__ outH, int K, int N, int actflag) {
    extern __shared__ __align__(1024) char smem[];
    uint32_t sb = smem_u32(smem);
    int tid = threadIdx.x, lid = tid & 31, wid = tid >> 5;
    int wm = wid >> 1, wn = wid & 1;            // 2 x 2 warps, warp tile 64x64
    int m0 = blockIdx.y * BM, n0 = blockIdx.x * BN;
    int niter = K / BK;

    // ldmatrix lane addressing
    int arow = wm * 64 + (lid & 7) + ((lid >> 3) & 1) * 8;  // + mi*16
    int ahalf = lid >> 4;
    int brow = wn * 64 + (lid & 7) + (lid >> 4) * 8;        // + nj*16
    int bhalf = (lid >> 3) & 1;

    float acc[4][8][4];
    #pragma unroll
    for (int mi = 0; mi < 4; mi++)
        #pragma unroll
        for (int nt = 0; nt < 8; nt++)
            #pragma unroll
            for (int q = 0; q < 4; q++) acc[mi][nt][q] = 0.f;

    // prologue: stages 0,1
    load_stage(sb, 0, 0, A, W, K, m0, n0, tid);
    asm volatile("cp.async.commit_group;" ::: "memory");
    load_stage(sb, 1, 1, A, W, K, m0, n0, tid);
    asm volatile("cp.async.commit_group;" ::: "memory");

    int s = 0, sp = 2;   // consume stage, prefetch stage (mod 3)
    for (int it = 0; it < niter; it++) {
        asm volatile("cp.async.wait_group 1;" ::: "memory");
        __syncthreads();
        int ldc = it + 2;
        if (ldc < niter) load_stage(sb, sp, ldc, A, W, K, m0, n0, tid);
        asm volatile("cp.async.commit_group;" ::: "memory");

        uint32_t aS = sb + s * ST_BYTES;
        uint32_t bS = aS + A_ST;

        #pragma unroll
        for (int ks = 0; ks < 4; ks++) {          // 4 x k16 per 64-K stage
            uint32_t a[4][4], b[4][4];
            #pragma unroll
            for (int mi = 0; mi < 4; mi++) {
                int r = arow + mi * 16;
                uint32_t ad = aS + r * 128 + ((((ks << 1) | ahalf) ^ (r & 7)) << 4);
                LDMX4(a[mi], ad);
            }
            #pragma unroll
            for (int nj = 0; nj < 4; nj++) {
                int r = brow + nj * 16;
                uint32_t ad = bS + r * 128 + ((((ks << 1) | bhalf) ^ (r & 7)) << 4);
                LDMX4(b[nj], ad);
            }
            #pragma unroll
            for (int mi = 0; mi < 4; mi++)
                #pragma unroll
                for (int nt = 0; nt < 8; nt++)
                    MMAB16(acc[mi][nt], a[mi],
                           b[nt >> 1][(nt & 1) * 2],
                           b[nt >> 1][(nt & 1) * 2 + 1]);
        }
        s = (s + 1 == NST) ? 0 : s + 1;
        sp = (sp + 1 == NST) ? 0 : sp + 1;
    }

    // epilogue
    int grow = lid >> 2, gcol = (lid & 3) * 2;
    #pragma unroll
    for (int mi = 0; mi < 4; mi++) {
        #pragma unroll
        for (int nt = 0; nt < 8; nt++) {
            int m = m0 + wm * 64 + mi * 16 + grow;
            int c = n0 + wn * 64 + nt * 8 + gcol;
            float b0 = __ldg(bias + c), b1 = __ldg(bias + c + 1);
            float f0 = acc[mi][nt][0] + b0, f1 = acc[mi][nt][1] + b1;
            float f2 = acc[mi][nt][2] + b0, f3 = acc[mi][nt][3] + b1;
            if (actflag) {
                __nv_bfloat162 h0, h1;
                h0.x = __float2bfloat16_rn(fmaxf(f0, 0.f));
                h0.y = __float2bfloat16_rn(fmaxf(f1, 0.f));
                h1.x = __float2bfloat16_rn(fmaxf(f2, 0.f));
                h1.y = __float2bfloat16_rn(fmaxf(f3, 0.f));
                *(__nv_bfloat162*)(outH + (size_t)m * N + c)       = h0;
                *(__nv_bfloat162*)(outH + (size_t)(m + 8) * N + c) = h1;
            } else {
                *(float2*)(outF + (size_t)m * N + c)       = make_float2(f0, f1);
                *(float2*)(outF + (size_t)(m + 8) * N + c) = make_float2(f2, f3);
            }
        }
    }
}

// ---------------- host ----------------
extern "C" void kernel_launch(void* const* d_in, const int* in_sizes, int n_in,
                              void* d_out, int out_size) {
    (void)in_sizes; (void)n_in; (void)out_size;
    const int Ks[4] = {2048, 4096, 4096, 4096};
    const int Ns[4] = {4096, 4096, 4096, 2048};
    const float* x = (const float*)d_in[0];

    __nv_bfloat16 *actP, *actQ, *wt;
    float *bias, *ea, *eb;
    cudaGetSymbolAddress((void**)&actP, g_actP);
    cudaGetSymbolAddress((void**)&actQ, g_actQ);
    cudaGetSymbolAddress((void**)&wt,   g_wt);
    cudaGetSymbolAddress((void**)&bias, g_bias);
    cudaGetSymbolAddress((void**)&ea,   g_ea);
    cudaGetSymbolAddress((void**)&eb,   g_eb);
    cudaFuncSetAttribute(gemm_k, cudaFuncAttributeMaxDynamicSharedMemorySize, SMEM_SZ);

    // My launch order: 0 cvt, 1 expfuse0, 2 build0, 3 gemm0, ...
    // Harness prepends 2 launches -> ncu -s 5 -c 1 samples gemm0.
    int n4 = 8192 * 2048 / 4;
    cvt_k<<<(n4 + 255) / 256, 256>>>(x, actQ, n4);

    for (int i = 0; i < 4; i++) {
        const float* Mi = (const float*)d_in[1 + 4 * i];
        const float* ui = (const float*)d_in[2 + 4 * i];
        const float* vi = (const float*)d_in[3 + 4 * i];
        const float* Ei = (const float*)d_in[4 + 4 * i];
        int K = Ks[i], N = Ns[i];

        int ne = (K + 1 > N) ? K + 1 : N;
        expfuse_k<<<(ne + 255) / 256, 256>>>(ui, vi, ea, eb, K + 1, N);
        build_k<<<dim3(N / 32, K / 32 + 1), dim3(32, 8)>>>(Mi, Ei, ea, eb, wt, bias, K, N);

        const __nv_bfloat16* Ain = (i % 2 == 0) ? actQ : actP;
        __nv_bfloat16* OH = (i % 2 == 0) ? actP : actQ;
        float* OF = (i == 3) ? (float*)d_out : nullptr;
        int actflag = (i < 3) ? 1 : 0;
        gemm_k<<<dim3(N / BN, 8192 / BM), NTHR, SMEM_SZ>>>(Ain, wt, bias, OF, OH, K, N, actflag);
    }
}

// round 17
// speedup vs baseline: 1.0373x; 1.0373x over previous
#include <cuda_runtime.h>
#include <cuda_bf16.h>
#include <cstdint>
#include <cstddef>

// ---------------- tile config ----------------
#define BM 128
#define BN 128
#define BK 64                        // bf16 per K-chunk (128 B rows)
#define NST 3
#define NTHR 256
#define A_ST (BM*BK*2)               // 16384 B
#define B_ST (BN*BK*2)               // 16384 B
#define ST_BYTES (A_ST + B_ST)       // 32768 B
#define SMEM_SZ (NST*ST_BYTES)       // 98304 B  (x2 CTAs = 196KB/SM)

// ---------------- static scratch (no allocations allowed) ----------------
__device__ __nv_bfloat16 g_actP[(size_t)8192*4096];
__device__ __nv_bfloat16 g_actQ[(size_t)8192*4096];
__device__ __nv_bfloat16 g_wtA[(size_t)4096*4096];
__device__ __nv_bfloat16 g_wtB[(size_t)4096*4096];
__device__ float g_biasA[4096];
__device__ float g_biasB[4096];

// ---------------- helpers ----------------
__device__ __forceinline__ uint32_t smem_u32(const void* p) {
    uint32_t a;
    asm("{ .reg .u64 t; cvta.to.shared.u64 t, %1; cvt.u32.u64 %0, t; }" : "=r"(a) : "l"(p));
    return a;
}
__device__ __forceinline__ void cpa16(uint32_t s, const void* g) {
    asm volatile("cp.async.cg.shared.global [%0], [%1], 16;" :: "r"(s), "l"(g) : "memory");
}
#define LDMX4(r, addr) \
    asm volatile("ldmatrix.sync.aligned.m8n8.x4.shared.b16 {%0,%1,%2,%3}, [%4];" \
        : "=r"((r)[0]), "=r"((r)[1]), "=r"((r)[2]), "=r"((r)[3]) : "r"(addr))
#define MMAB16(c, a, b0, b1) \
    asm volatile("mma.sync.aligned.m16n8k16.row.col.f32.bf16.bf16.f32 " \
        "{%0,%1,%2,%3},{%4,%5,%6,%7},{%8,%9},{%0,%1,%2,%3};" \
        : "+f"((c)[0]), "+f"((c)[1]), "+f"((c)[2]), "+f"((c)[3]) \
        : "r"((a)[0]), "r"((a)[1]), "r"((a)[2]), "r"((a)[3]), "r"(b0), "r"(b1))

// one k16-step: LDSM + 16 MMAs (R13 warp tile 64x32)
#define KSTEP(ks) do { \
    uint32_t a[4][4], b[2][4]; \
    _Pragma("unroll") \
    for (int mi = 0; mi < 4; mi++) { \
        int r = arow + mi * 16; \
        uint32_t ad = aS + r * 128 + (((((ks) << 1) | ahalf) ^ (r & 7)) << 4); \
        LDMX4(a[mi], ad); \
    } \
    _Pragma("unroll") \
    for (int nj = 0; nj < 2; nj++) { \
        int r = brow + nj * 16; \
        uint32_t ad = bS + r * 128 + (((((ks) << 1) | bhalf) ^ (r & 7)) << 4); \
        LDMX4(b[nj], ad); \
    } \
    _Pragma("unroll") \
    for (int mi = 0; mi < 4; mi++) \
        _Pragma("unroll") \
        for (int nt = 0; nt < 4; nt++) \
            MMAB16(acc[mi][nt], a[mi], \
                   b[nt >> 1][(nt & 1) * 2], \
                   b[nt >> 1][(nt & 1) * 2 + 1]); \
} while (0)

// ---------------- small kernels ----------------
__global__ void cvt_k(const float* __restrict__ in, __nv_bfloat16* __restrict__ out, int n4) {
    int i = blockIdx.x * blockDim.x + threadIdx.x;
    if (i < n4) {
        float4 v = ((const float4*)in)[i];
        __nv_bfloat162 h0, h1;
        h0.x = __float2bfloat16_rn(v.x); h0.y = __float2bfloat16_rn(v.y);
        h1.x = __float2bfloat16_rn(v.z); h1.y = __float2bfloat16_rn(v.w);
        ((__nv_bfloat162*)out)[2*i]   = h0;
        ((__nv_bfloat162*)out)[2*i+1] = h1;
    }
}

// W^T build with fused exp: read M/eps row-major [fin,N] + u,v raw;
// write wt [N,K] K-major (bf16) + bias (fp32)
__global__ void build_k(const float* __restrict__ M, const float* __restrict__ E,
                        const float* __restrict__ u, const float* __restrict__ v,
                        __nv_bfloat16* __restrict__ wt, float* __restrict__ bias,
                        int K, int N) {
    __shared__ float t[32][33];
    int c0 = blockIdx.x * 32, r0 = blockIdx.y * 32;
    int tx = threadIdx.x, ty = threadIdx.y;
    int c = c0 + tx;
    float ebc = expf(0.5f * v[c]);
    #pragma unroll
    for (int i = 0; i < 4; i++) {
        int r = r0 + ty + i * 8;
        if (r <= K) {
            float ear = expf(0.5f * u[r]);
            size_t idx = (size_t)r * N + c;
            float val = fmaf(ear * E[idx], ebc, M[idx]);
            if (r < K) t[ty + i * 8][tx] = val;
            else       bias[c] = val;
        }
    }
    __syncthreads();
    #pragma unroll
    for (int i = 0; i < 4; i++) {
        int n = c0 + ty + i * 8;
        int k = r0 + tx;
        if (k < K) wt[(size_t)n * K + k] = __float2bfloat16_rn(t[tx][ty + i * 8]);
    }
}

// ---------------- GEMM: C[8192,N] = A[8192,K] @ W^T + bias (+relu) ----------------
__device__ __forceinline__ void load_stage(uint32_t sb, int stage, int kc,
    const __nv_bfloat16* __restrict__ A, const __nv_bfloat16* __restrict__ W,
    int K, int m0, int n0, int tid) {
    const __nv_bfloat16* ga = A + (size_t)m0 * K + (size_t)kc * BK;
    uint32_t ab = sb + stage * ST_BYTES;
    #pragma unroll
    for (int j = 0; j < 4; j++) {
        int idx = tid + j * NTHR;
        int row = idx >> 3, c16 = idx & 7;
        uint32_t off = (uint32_t)(row * 128 + ((c16 ^ (row & 7)) << 4));
        cpa16(ab + off, ga + (size_t)row * K + c16 * 8);
    }
    const __nv_bfloat16* gb = W + (size_t)n0 * K + (size_t)kc * BK;
    uint32_t bb = ab + A_ST;
    #pragma unroll
    for (int j = 0; j < 4; j++) {
        int idx = tid + j * NTHR;
        int row = idx >> 3, c16 = idx & 7;
        uint32_t off = (uint32_t)(row * 128 + ((c16 ^ (row & 7)) << 4));
        cpa16(bb + off, gb + (size_t)row * K + c16 * 8);
    }
}

__global__ void __launch_bounds__(NTHR, 2) gemm_k(
    const __nv_bfloat16* __restrict__ A, const __nv_bfloat16* __restrict__ W,
    const float* __restrict__ bias, float* __restrict__ outF,
    __nv_bfloat16* __restrict__ outH, int K, int N, int actflag) {
    extern __shared__ __align__(1024) char smem[];
    uint32_t sb = smem_u32(smem);
    int tid = threadIdx.x, lid = tid & 31, wid = tid >> 5;
    int wm = wid >> 2, wn = wid & 3;            // 2 x 4 warps, warp tile 64x32
    int m0 = blockIdx.y * BM, n0 = blockIdx.x * BN;
    int niter = K / BK;

    int arow = wm * 64 + (lid & 7) + ((lid >> 3) & 1) * 8;
    int ahalf = lid >> 4;
    int brow = wn * 32 + (lid & 7) + (lid >> 4) * 8;
    int bhalf = (lid >> 3) & 1;

    float acc[4][4][4];
    #pragma unroll
    for (int mi = 0; mi < 4; mi++)
        #pragma unroll
        for (int nt = 0; nt < 4; nt++)
            #pragma unroll
            for (int q = 0; q < 4; q++) acc[mi][nt][q] = 0.f;

    // prologue: stages 0,1
    load_stage(sb, 0, 0, A, W, K, m0, n0, tid);
    asm volatile("cp.async.commit_group;" ::: "memory");
    load_stage(sb, 1, 1, A, W, K, m0, n0, tid);
    asm volatile("cp.async.commit_group;" ::: "memory");

    int s = 0, sp = 2;
    for (int it = 0; it < niter; it++) {
        asm volatile("cp.async.wait_group 1;" ::: "memory");
        __syncthreads();

        uint32_t aS = sb + s * ST_BYTES;
        uint32_t bS = aS + A_ST;

        // ks=0 first: fill the tensor pipe before the cp.async issue burst
        KSTEP(0);

        // next-stage loads issue while ks=0's MMAs drain in the pipe
        int ldc = it + 2;
        if (ldc < niter) load_stage(sb, sp, ldc, A, W, K, m0, n0, tid);
        asm volatile("cp.async.commit_group;" ::: "memory");

        KSTEP(1);
        KSTEP(2);
        KSTEP(3);

        s = (s + 1 == NST) ? 0 : s + 1;
        sp = (sp + 1 == NST) ? 0 : sp + 1;
    }

    // epilogue
    int grow = lid >> 2, gcol = (lid & 3) * 2;
    #pragma unroll
    for (int mi = 0; mi < 4; mi++) {
        #pragma unroll
        for (int nt = 0; nt < 4; nt++) {
            int m = m0 + wm * 64 + mi * 16 + grow;
            int c = n0 + wn * 32 + nt * 8 + gcol;
            float b0 = __ldg(bias + c), b1 = __ldg(bias + c + 1);
            float f0 = acc[mi][nt][0] + b0, f1 = acc[mi][nt][1] + b1;
            float f2 = acc[mi][nt][2] + b0, f3 = acc[mi][nt][3] + b1;
            if (actflag) {
                __nv_bfloat162 h0, h1;
                h0.x = __float2bfloat16_rn(fmaxf(f0, 0.f));
                h0.y = __float2bfloat16_rn(fmaxf(f1, 0.f));
                h1.x = __float2bfloat16_rn(fmaxf(f2, 0.f));
                h1.y = __float2bfloat16_rn(fmaxf(f3, 0.f));
                *(__nv_bfloat162*)(outH + (size_t)m * N + c)       = h0;
                *(__nv_bfloat162*)(outH + (size_t)(m + 8) * N + c) = h1;
            } else {
                *(float2*)(outF + (size_t)m * N + c)       = make_float2(f0, f1);
                *(float2*)(outF + (size_t)(m + 8) * N + c) = make_float2(f2, f3);
            }
        }
    }
}

// ---------------- host ----------------
extern "C" void kernel_launch(void* const* d_in, const int* in_sizes, int n_in,
                              void* d_out, int out_size) {
    (void)in_sizes; (void)n_in; (void)out_size;
    const int Ks[4] = {2048, 4096, 4096, 4096};
    const int Ns[4] = {4096, 4096, 4096, 2048};
    const float* x = (const float*)d_in[0];

    __nv_bfloat16 *actP, *actQ, *wtA, *wtB;
    float *biasA, *biasB;
    cudaGetSymbolAddress((void**)&actP,  g_actP);
    cudaGetSymbolAddress((void**)&actQ,  g_actQ);
    cudaGetSymbolAddress((void**)&wtA,   g_wtA);
    cudaGetSymbolAddress((void**)&wtB,   g_wtB);
    cudaGetSymbolAddress((void**)&biasA, g_biasA);
    cudaGetSymbolAddress((void**)&biasB, g_biasB);
    cudaFuncSetAttribute(gemm_k, cudaFuncAttributeMaxDynamicSharedMemorySize, SMEM_SZ);

    const float* Ms[4]; const float* us[4]; const float* vs[4]; const float* Es[4];
    for (int i = 0; i < 4; i++) {
        Ms[i] = (const float*)d_in[1 + 4 * i];
        us[i] = (const float*)d_in[2 + 4 * i];
        vs[i] = (const float*)d_in[3 + 4 * i];
        Es[i] = (const float*)d_in[4 + 4 * i];
    }
    __nv_bfloat16* wts[4]  = {wtA, wtB, wtA, wtB};
    float*         biass[4] = {biasA, biasB, biasA, biasB};

    // Launch order: 0 cvt, 1 build0, 2 build1, 3 gemm0, 4 gemm1,
    //               5 build2, 6 gemm2, 7 build3, 8 gemm3.
    // Harness prepends 2 launches -> ncu -s 5 -c 1 samples gemm0 (my idx 3).
    int n4 = 8192 * 2048 / 4;
    cvt_k<<<(n4 + 255) / 256, 256>>>(x, actQ, n4);                                        // 0

    build_k<<<dim3(Ns[0] / 32, Ks[0] / 32 + 1), dim3(32, 8)>>>(Ms[0], Es[0], us[0], vs[0],
                                                               wts[0], biass[0], Ks[0], Ns[0]); // 1
    build_k<<<dim3(Ns[1] / 32, Ks[1] / 32 + 1), dim3(32, 8)>>>(Ms[1], Es[1], us[1], vs[1],
                                                               wts[1], biass[1], Ks[1], Ns[1]); // 2

    for (int i = 0; i < 4; i++) {
        if (i >= 2) {
            build_k<<<dim3(Ns[i] / 32, Ks[i] / 32 + 1), dim3(32, 8)>>>(Ms[i], Es[i], us[i], vs[i],
                                                                       wts[i], biass[i], Ks[i], Ns[i]);
        }
        const __nv_bfloat16* Ain = (i % 2 == 0) ? actQ : actP;
        __nv_bfloat16* OH = (i % 2 == 0) ? actP : actQ;
        float* OF = (i == 3) ? (float*)d_out : nullptr;
        int actflag = (i < 3) ? 1 : 0;
        gemm_k<<<dim3(Ns[i] / BN, 8192 / BM), NTHR, SMEM_SZ>>>(Ain, wts[i], biass[i],
                                                               OF, OH, Ks[i], Ns[i], actflag);
    }
}